// round 1
// baseline (speedup 1.0000x reference)
#include <cuda_runtime.h>
#include <math.h>

#define S_DIM 16
#define B_DIM 512
#define H_DIM 2048
#define EPS 1e-8f

// Scratch (allocations are forbidden; __device__ globals are the sanctioned path)
__device__ float g_sims[S_DIM * B_DIM];     // sims[s][b] * (1/S)
__device__ float g_onorm[B_DIM];            // ||OG[b]||
__device__ float g_wr[B_DIM * H_DIM];       // weightedRep (B,H)

// ---------------------------------------------------------------------------
// packed f32x2 helpers (Blackwell PTX)
// ---------------------------------------------------------------------------
__device__ __forceinline__ unsigned long long pack2(float x, float y) {
    unsigned long long r;
    asm("mov.b64 %0, {%1, %2};" : "=l"(r) : "f"(x), "f"(y));
    return r;
}
__device__ __forceinline__ void unpack2(unsigned long long v, float& x, float& y) {
    asm("mov.b64 {%0, %1}, %2;" : "=f"(x), "=f"(y) : "l"(v));
}
__device__ __forceinline__ void ffma2(unsigned long long& d,
                                      unsigned long long a,
                                      unsigned long long b) {
    asm("fma.rn.f32x2 %0, %1, %2, %0;" : "+l"(d) : "l"(a), "l"(b));
}

// ---------------------------------------------------------------------------
// Kernel 1: o_norm[b] = ||OG[b]||   (512 blocks x 256 threads)
// ---------------------------------------------------------------------------
__global__ void onorm_kernel(const float* __restrict__ og) {
    const int b = blockIdx.x;
    const float4* row = reinterpret_cast<const float4*>(og + (size_t)b * H_DIM);
    float s = 0.f;
    for (int i = threadIdx.x; i < H_DIM / 4; i += 256) {
        float4 v = row[i];
        s += v.x * v.x + v.y * v.y + v.z * v.z + v.w * v.w;
    }
    #pragma unroll
    for (int o = 16; o; o >>= 1) s += __shfl_xor_sync(0xffffffffu, s, o);
    __shared__ float red[8];
    if ((threadIdx.x & 31) == 0) red[threadIdx.x >> 5] = s;
    __syncthreads();
    if (threadIdx.x < 32) {
        float v = (threadIdx.x < 8) ? red[threadIdx.x] : 0.f;
        #pragma unroll
        for (int o = 4; o; o >>= 1) v += __shfl_xor_sync(0xffffffffu, v, o);
        if (threadIdx.x == 0) g_onorm[b] = sqrtf(v);
    }
}

// ---------------------------------------------------------------------------
// Kernel 2: sims[s][b] = dot(e[s,b], og[b]) / max(||e[s,b]|| * ||og[b]||, EPS) / S
// grid (B, S), 256 threads. Streaming pass over enhanced (64 MB) — HBM bound.
// ---------------------------------------------------------------------------
__global__ void sims_kernel(const float* __restrict__ og,
                            const float* __restrict__ enh) {
    const int b = blockIdx.x;
    const int s = blockIdx.y;
    const float4* e = reinterpret_cast<const float4*>(
        enh + ((size_t)s * B_DIM + b) * H_DIM);
    const float4* o = reinterpret_cast<const float4*>(og + (size_t)b * H_DIM);

    float dot = 0.f, e2 = 0.f;
    for (int i = threadIdx.x; i < H_DIM / 4; i += 256) {
        float4 ev = e[i];
        float4 ov = o[i];
        dot += ev.x * ov.x + ev.y * ov.y + ev.z * ov.z + ev.w * ov.w;
        e2  += ev.x * ev.x + ev.y * ev.y + ev.z * ev.z + ev.w * ev.w;
    }
    #pragma unroll
    for (int off = 16; off; off >>= 1) {
        dot += __shfl_xor_sync(0xffffffffu, dot, off);
        e2  += __shfl_xor_sync(0xffffffffu, e2, off);
    }
    __shared__ float rd[8], re[8];
    if ((threadIdx.x & 31) == 0) {
        rd[threadIdx.x >> 5] = dot;
        re[threadIdx.x >> 5] = e2;
    }
    __syncthreads();
    if (threadIdx.x < 32) {
        float d = (threadIdx.x < 8) ? rd[threadIdx.x] : 0.f;
        float q = (threadIdx.x < 8) ? re[threadIdx.x] : 0.f;
        #pragma unroll
        for (int off = 4; off; off >>= 1) {
            d += __shfl_xor_sync(0xffffffffu, d, off);
            q += __shfl_xor_sync(0xffffffffu, q, off);
        }
        if (threadIdx.x == 0) {
            float denom = fmaxf(sqrtf(q) * g_onorm[b], EPS);
            g_sims[s * B_DIM + b] = (d / denom) * (1.0f / S_DIM);
        }
    }
}

// ---------------------------------------------------------------------------
// Kernel 3: weightedRep[b,h] = sum_s enhanced[s,b,h] * sims[s][b]  (1/S folded in)
// float4 over B*H; second pass over enhanced should hit L2 (64 MB < 126 MB).
// ---------------------------------------------------------------------------
__global__ void wr_kernel(const float* __restrict__ enh) {
    const int i = blockIdx.x * 256 + threadIdx.x;      // float4 index in [0, B*H/4)
    const int b = i / (H_DIM / 4);
    const float4* e = reinterpret_cast<const float4*>(enh);
    const size_t stride = (size_t)B_DIM * H_DIM / 4;

    float4 acc = make_float4(0.f, 0.f, 0.f, 0.f);
    #pragma unroll
    for (int s = 0; s < S_DIM; s++) {
        const float w = g_sims[s * B_DIM + b];
        float4 v = e[(size_t)s * stride + i];
        acc.x += v.x * w;
        acc.y += v.y * w;
        acc.z += v.z * w;
        acc.w += v.w * w;
    }
    reinterpret_cast<float4*>(g_wr)[i] = acc;
}

// ---------------------------------------------------------------------------
// Kernel 4: out = weightedRep @ W^T + b
// M=512 (rows of wr), N=2048 (rows of W), K=2048. Both operands K-major.
// 64x64 block tile, BK=32, 256 threads, 4(M)x4(N) micro-tile, packed FFMA2.
// ---------------------------------------------------------------------------
#define BM 64
#define BN 64
#define BK 32
#define LDP 68   // padded smem row stride (floats); 272B, 16B-aligned

__global__ void __launch_bounds__(256, 4)
gemm_kernel(const float* __restrict__ Wm,
            const float* __restrict__ bias,
            float* __restrict__ out) {
    __shared__ float As[BK][LDP];   // As[k][m]
    __shared__ float Bs[BK][LDP];   // Bs[k][n]

    const int bn = blockIdx.x;      // N tile
    const int bm = blockIdx.y;      // M tile
    const int tid = threadIdx.x;
    const int tx = tid & 15;        // -> N (fast, for coalesced stores)
    const int ty = tid >> 4;        // -> M

    const float* A  = g_wr + (size_t)bm * BM * H_DIM;
    const float* Bp = Wm   + (size_t)bn * BN * H_DIM;

    // loader mapping: each thread loads 2 float4 from each of A and B per tile
    const int lrow = tid >> 2;      // 0..63
    const int lk4  = tid & 3;       // float4 slot 0..3 (second pass +4)

    unsigned long long acc[4][2];
    #pragma unroll
    for (int mi = 0; mi < 4; mi++)
        #pragma unroll
        for (int nj = 0; nj < 2; nj++) acc[mi][nj] = 0ull;

    for (int k0 = 0; k0 < H_DIM; k0 += BK) {
        #pragma unroll
        for (int l = 0; l < 2; l++) {
            const int kq = lk4 + l * 4;                // float4 index in [0,8)
            float4 av = *reinterpret_cast<const float4*>(
                A + (size_t)lrow * H_DIM + k0 + kq * 4);
            As[kq * 4 + 0][lrow] = av.x;
            As[kq * 4 + 1][lrow] = av.y;
            As[kq * 4 + 2][lrow] = av.z;
            As[kq * 4 + 3][lrow] = av.w;
            float4 bv = *reinterpret_cast<const float4*>(
                Bp + (size_t)lrow * H_DIM + k0 + kq * 4);
            Bs[kq * 4 + 0][lrow] = bv.x;
            Bs[kq * 4 + 1][lrow] = bv.y;
            Bs[kq * 4 + 2][lrow] = bv.z;
            Bs[kq * 4 + 3][lrow] = bv.w;
        }
        __syncthreads();

        #pragma unroll
        for (int k = 0; k < BK; k++) {
            float4 af = *reinterpret_cast<const float4*>(&As[k][ty * 4]);
            float4 bf = *reinterpret_cast<const float4*>(&Bs[k][tx * 4]);
            unsigned long long b0 = pack2(bf.x, bf.y);
            unsigned long long b1 = pack2(bf.z, bf.w);
            unsigned long long a0 = pack2(af.x, af.x);
            unsigned long long a1 = pack2(af.y, af.y);
            unsigned long long a2 = pack2(af.z, af.z);
            unsigned long long a3 = pack2(af.w, af.w);
            ffma2(acc[0][0], a0, b0); ffma2(acc[0][1], a0, b1);
            ffma2(acc[1][0], a1, b0); ffma2(acc[1][1], a1, b1);
            ffma2(acc[2][0], a2, b0); ffma2(acc[2][1], a2, b1);
            ffma2(acc[3][0], a3, b0); ffma2(acc[3][1], a3, b1);
        }
        __syncthreads();
    }

    // epilogue: add bias, store float4 (coalesced along N within warp)
    const int n = bn * BN + tx * 4;
    const float4 bias4 = *reinterpret_cast<const float4*>(bias + n);
    #pragma unroll
    for (int mi = 0; mi < 4; mi++) {
        const int m = bm * BM + ty * 4 + mi;
        float r0, r1, r2, r3;
        unpack2(acc[mi][0], r0, r1);
        unpack2(acc[mi][1], r2, r3);
        float4 rv = make_float4(r0 + bias4.x, r1 + bias4.y,
                                r2 + bias4.z, r3 + bias4.w);
        *reinterpret_cast<float4*>(out + (size_t)m * H_DIM + n) = rv;
    }
}

// ---------------------------------------------------------------------------
extern "C" void kernel_launch(void* const* d_in, const int* in_sizes, int n_in,
                              void* d_out, int out_size) {
    const float* og   = (const float*)d_in[0];   // (B, H)
    const float* enh  = (const float*)d_in[1];   // (S, B, H)
    const float* Wm   = (const float*)d_in[2];   // (H, H)
    const float* bias = (const float*)d_in[3];   // (H,)
    float* out = (float*)d_out;                  // (B, H)

    onorm_kernel<<<B_DIM, 256>>>(og);
    sims_kernel<<<dim3(B_DIM, S_DIM), 256>>>(og, enh);
    wr_kernel<<<(B_DIM * H_DIM / 4) / 256, 256>>>(enh);
    gemm_kernel<<<dim3(H_DIM / BN, B_DIM / BM), 256>>>(Wm, bias, out);
}

// round 3
// speedup vs baseline: 2.0125x; 2.0125x over previous
#include <cuda_runtime.h>
#include <cuda_bf16.h>
#include <math.h>
#include <stdint.h>

#define S_DIM 16
#define B_DIM 512
#define H_DIM 2048
#define EPS 1e-8f

// ---------------------------------------------------------------------------
// Device scratch
// ---------------------------------------------------------------------------
__device__ float g_sims[S_DIM * B_DIM];                       // sims * (1/S)
__device__ float g_onorm[B_DIM];
__device__ __align__(16) __nv_bfloat16 g_Ahi[B_DIM * H_DIM];
__device__ __align__(16) __nv_bfloat16 g_Alo[B_DIM * H_DIM];
__device__ __align__(16) __nv_bfloat16 g_Whi[H_DIM * H_DIM];
__device__ __align__(16) __nv_bfloat16 g_Wlo[H_DIM * H_DIM];

// ---------------------------------------------------------------------------
// PTX helpers (sm_80/90 baseline only — NO tcgen05, harness PTX target lacks 'a')
// ---------------------------------------------------------------------------
__device__ __forceinline__ uint32_t smem_u32(const void* p) {
    uint32_t r;
    asm("{ .reg .u64 t; cvta.to.shared.u64 t, %1; cvt.u32.u64 %0, t; }"
        : "=r"(r) : "l"(p));
    return r;
}
__device__ __forceinline__ void cpa16(uint32_t dst, const void* src) {
    asm volatile("cp.async.cg.shared.global [%0], [%1], 16;" :: "r"(dst), "l"(src));
}
#define CP_COMMIT() asm volatile("cp.async.commit_group;" ::: "memory")
#define CP_WAIT2()  asm volatile("cp.async.wait_group 2;" ::: "memory")

__device__ __forceinline__ void ldsm4(uint32_t* r, uint32_t addr) {
    asm volatile("ldmatrix.sync.aligned.m8n8.x4.shared.b16 {%0,%1,%2,%3}, [%4];"
                 : "=r"(r[0]), "=r"(r[1]), "=r"(r[2]), "=r"(r[3]) : "r"(addr));
}
__device__ __forceinline__ void mma16816(float* d, const uint32_t* a,
                                         uint32_t b0, uint32_t b1) {
    asm volatile(
        "mma.sync.aligned.m16n8k16.row.col.f32.bf16.bf16.f32 "
        "{%0,%1,%2,%3}, {%4,%5,%6,%7}, {%8,%9}, {%0,%1,%2,%3};"
        : "+f"(d[0]), "+f"(d[1]), "+f"(d[2]), "+f"(d[3])
        : "r"(a[0]), "r"(a[1]), "r"(a[2]), "r"(a[3]), "r"(b0), "r"(b1));
}

// ---------------------------------------------------------------------------
// Kernel 1: o_norm[b] = ||OG[b]||
// ---------------------------------------------------------------------------
__global__ void onorm_kernel(const float* __restrict__ og) {
    const int b = blockIdx.x;
    const float4* row = reinterpret_cast<const float4*>(og + (size_t)b * H_DIM);
    float s = 0.f;
    for (int i = threadIdx.x; i < H_DIM / 4; i += 256) {
        float4 v = row[i];
        s += v.x * v.x + v.y * v.y + v.z * v.z + v.w * v.w;
    }
    #pragma unroll
    for (int o = 16; o; o >>= 1) s += __shfl_xor_sync(0xffffffffu, s, o);
    __shared__ float red[8];
    if ((threadIdx.x & 31) == 0) red[threadIdx.x >> 5] = s;
    __syncthreads();
    if (threadIdx.x < 32) {
        float v = (threadIdx.x < 8) ? red[threadIdx.x] : 0.f;
        #pragma unroll
        for (int o = 4; o; o >>= 1) v += __shfl_xor_sync(0xffffffffu, v, o);
        if (threadIdx.x == 0) g_onorm[b] = sqrtf(v);
    }
}

// ---------------------------------------------------------------------------
// Kernel 2: sims[s][b] (1/S folded in)
// ---------------------------------------------------------------------------
__global__ void sims_kernel(const float* __restrict__ og,
                            const float* __restrict__ enh) {
    const int b = blockIdx.x;
    const int s = blockIdx.y;
    const float4* e = reinterpret_cast<const float4*>(
        enh + ((size_t)s * B_DIM + b) * H_DIM);
    const float4* o = reinterpret_cast<const float4*>(og + (size_t)b * H_DIM);

    float dot = 0.f, e2 = 0.f;
    for (int i = threadIdx.x; i < H_DIM / 4; i += 256) {
        float4 ev = e[i];
        float4 ov = o[i];
        dot += ev.x * ov.x + ev.y * ov.y + ev.z * ov.z + ev.w * ov.w;
        e2  += ev.x * ev.x + ev.y * ev.y + ev.z * ev.z + ev.w * ev.w;
    }
    #pragma unroll
    for (int off = 16; off; off >>= 1) {
        dot += __shfl_xor_sync(0xffffffffu, dot, off);
        e2  += __shfl_xor_sync(0xffffffffu, e2, off);
    }
    __shared__ float rd[8], re[8];
    if ((threadIdx.x & 31) == 0) {
        rd[threadIdx.x >> 5] = dot;
        re[threadIdx.x >> 5] = e2;
    }
    __syncthreads();
    if (threadIdx.x < 32) {
        float d = (threadIdx.x < 8) ? rd[threadIdx.x] : 0.f;
        float q = (threadIdx.x < 8) ? re[threadIdx.x] : 0.f;
        #pragma unroll
        for (int off = 4; off; off >>= 1) {
            d += __shfl_xor_sync(0xffffffffu, d, off);
            q += __shfl_xor_sync(0xffffffffu, q, off);
        }
        if (threadIdx.x == 0) {
            float denom = fmaxf(sqrtf(q) * g_onorm[b], EPS);
            g_sims[s * B_DIM + b] = (d / denom) * (1.0f / S_DIM);
        }
    }
}

// ---------------------------------------------------------------------------
// Kernel 3: weightedRep -> bf16 hi/lo split
// ---------------------------------------------------------------------------
__global__ void wr_kernel(const float* __restrict__ enh) {
    const int i = blockIdx.x * 256 + threadIdx.x;      // float4 index
    const int b = i / (H_DIM / 4);
    const float4* e = reinterpret_cast<const float4*>(enh);
    const size_t stride = (size_t)B_DIM * H_DIM / 4;

    float4 acc = make_float4(0.f, 0.f, 0.f, 0.f);
    #pragma unroll
    for (int s = 0; s < S_DIM; s++) {
        const float w = g_sims[s * B_DIM + b];
        float4 v = e[(size_t)s * stride + i];
        acc.x += v.x * w; acc.y += v.y * w; acc.z += v.z * w; acc.w += v.w * w;
    }
    float vv[4] = {acc.x, acc.y, acc.z, acc.w};
    __nv_bfloat16 h[4], l[4];
    #pragma unroll
    for (int j = 0; j < 4; j++) {
        h[j] = __float2bfloat16(vv[j]);
        l[j] = __float2bfloat16(vv[j] - __bfloat162float(h[j]));
    }
    __nv_bfloat162* ph = reinterpret_cast<__nv_bfloat162*>(g_Ahi + (size_t)i * 4);
    __nv_bfloat162* pl = reinterpret_cast<__nv_bfloat162*>(g_Alo + (size_t)i * 4);
    ph[0] = __halves2bfloat162(h[0], h[1]);
    ph[1] = __halves2bfloat162(h[2], h[3]);
    pl[0] = __halves2bfloat162(l[0], l[1]);
    pl[1] = __halves2bfloat162(l[2], l[3]);
}

// ---------------------------------------------------------------------------
// Kernel 4: W -> bf16 hi/lo
// ---------------------------------------------------------------------------
__global__ void convw_kernel(const float* __restrict__ W) {
    const int i = blockIdx.x * 256 + threadIdx.x;
    float4 v4 = reinterpret_cast<const float4*>(W)[i];
    float vv[4] = {v4.x, v4.y, v4.z, v4.w};
    __nv_bfloat16 h[4], l[4];
    #pragma unroll
    for (int j = 0; j < 4; j++) {
        h[j] = __float2bfloat16(vv[j]);
        l[j] = __float2bfloat16(vv[j] - __bfloat162float(h[j]));
    }
    __nv_bfloat162* ph = reinterpret_cast<__nv_bfloat162*>(g_Whi + (size_t)i * 4);
    __nv_bfloat162* pl = reinterpret_cast<__nv_bfloat162*>(g_Wlo + (size_t)i * 4);
    ph[0] = __halves2bfloat162(h[0], h[1]);
    ph[1] = __halves2bfloat162(h[2], h[3]);
    pl[0] = __halves2bfloat162(l[0], l[1]);
    pl[1] = __halves2bfloat162(l[2], l[3]);
}

// ---------------------------------------------------------------------------
// Kernel 5: HMMA GEMM  out = wr @ W^T + b   (3-product bf16 split, fp32 accum)
// CTA tile 128(M) x 64(N), K-chunk 64, 3-stage cp.async pipeline.
// 8 warps, each 32x32 output via mma.sync.m16n8k16.
// smem rows padded to 72 elems (144B) -> conflict-free ldmatrix.
// ---------------------------------------------------------------------------
#define MT 128
#define NT 64
#define KT 64
#define NKC (H_DIM / KT)        // 32
#define LDS 144                 // bytes per smem row (72 bf16)
#define OFF_AHI 0
#define OFF_ALO (MT * LDS)                  // 18432
#define OFF_BHI (2 * MT * LDS)              // 36864
#define OFF_BLO (2 * MT * LDS + NT * LDS)   // 46080
#define STAGE   (2 * MT * LDS + 2 * NT * LDS)  // 55296
#define SM_GEMM (3 * STAGE)                    // 165888

__global__ void __launch_bounds__(256, 1)
gemm_hmma(const float* __restrict__ bias, float* __restrict__ out) {
    extern __shared__ __align__(16) char sm[];
    const uint32_t sbase = smem_u32(sm);
    const int tid = threadIdx.x;
    const int wid = tid >> 5;
    const int l   = tid & 31;
    const int bn = blockIdx.x;          // N tile (32)
    const int bm = blockIdx.y;          // M tile (4)

    const __nv_bfloat16* gAhi = g_Ahi + (size_t)bm * MT * H_DIM;
    const __nv_bfloat16* gAlo = g_Alo + (size_t)bm * MT * H_DIM;
    const __nv_bfloat16* gBhi = g_Whi + (size_t)bn * NT * H_DIM;
    const __nv_bfloat16* gBlo = g_Wlo + (size_t)bn * NT * H_DIM;

    // loader mapping: 256 threads, each 16B chunk: row = tid>>3, chunk = tid&7
    const int lrow = tid >> 3;          // 0..31
    const int lchk = tid & 7;           // 0..7 (8 elems each)

    auto load_stage = [&](int buf, int kb) {
        const uint32_t sb = sbase + buf * STAGE;
        const int koff = kb * KT + lchk * 8;
        #pragma unroll
        for (int rr = 0; rr < 4; rr++) {
            const int row = rr * 32 + lrow;
            const uint32_t d = sb + row * LDS + lchk * 16;
            cpa16(d + OFF_AHI, gAhi + (size_t)row * H_DIM + koff);
            cpa16(d + OFF_ALO, gAlo + (size_t)row * H_DIM + koff);
        }
        #pragma unroll
        for (int rr = 0; rr < 2; rr++) {
            const int row = rr * 32 + lrow;
            const uint32_t d = sb + row * LDS + lchk * 16;
            cpa16(d + OFF_BHI, gBhi + (size_t)row * H_DIM + koff);
            cpa16(d + OFF_BLO, gBlo + (size_t)row * H_DIM + koff);
        }
    };

    // prologue: fill 3 stages
    load_stage(0, 0); CP_COMMIT();
    load_stage(1, 1); CP_COMMIT();
    load_stage(2, 2); CP_COMMIT();

    // warp tile: m0 in {0,32,64,96}, n0 in {0,32}
    const int m0 = (wid & 3) * 32;
    const int n0 = (wid >> 2) * 32;

    // ldmatrix lane offsets (bytes within tile base)
    const uint32_t aoff = (uint32_t)(((l & 7) + ((l >> 3) & 1) * 8) * LDS
                                     + ((l >> 4) & 1) * 16);
    const uint32_t boff = (uint32_t)(((l & 7) + ((l >> 4) & 1) * 8) * LDS
                                     + ((l >> 3) & 1) * 16);

    float acc[2][4][4];
    #pragma unroll
    for (int mi = 0; mi < 2; mi++)
        #pragma unroll
        for (int nj = 0; nj < 4; nj++)
            #pragma unroll
            for (int q = 0; q < 4; q++) acc[mi][nj][q] = 0.f;

    for (int kc = 0; kc < NKC; kc++) {
        CP_WAIT2();
        __syncthreads();
        const int buf = kc % 3;
        const uint32_t sb = sbase + buf * STAGE;
        const uint32_t aHiB = sb + OFF_AHI + m0 * LDS + aoff;
        const uint32_t aLoB = sb + OFF_ALO + m0 * LDS + aoff;
        const uint32_t bHiB = sb + OFF_BHI + n0 * LDS + boff;
        const uint32_t bLoB = sb + OFF_BLO + n0 * LDS + boff;

        #pragma unroll
        for (int ks = 0; ks < 4; ks++) {
            uint32_t ah[2][4], al[2][4], bh[2][4], bl[2][4];
            #pragma unroll
            for (int mi = 0; mi < 2; mi++) {
                ldsm4(ah[mi], aHiB + mi * 16 * LDS + ks * 32);
                ldsm4(al[mi], aLoB + mi * 16 * LDS + ks * 32);
            }
            #pragma unroll
            for (int ng = 0; ng < 2; ng++) {
                ldsm4(bh[ng], bHiB + ng * 16 * LDS + ks * 32);
                ldsm4(bl[ng], bLoB + ng * 16 * LDS + ks * 32);
            }
            #pragma unroll
            for (int mi = 0; mi < 2; mi++) {
                #pragma unroll
                for (int nj = 0; nj < 4; nj++) {
                    const int ng = nj >> 1, sp = (nj & 1) * 2;
                    mma16816(acc[mi][nj], ah[mi], bh[ng][sp], bh[ng][sp + 1]);
                    mma16816(acc[mi][nj], ah[mi], bl[ng][sp], bl[ng][sp + 1]);
                    mma16816(acc[mi][nj], al[mi], bh[ng][sp], bh[ng][sp + 1]);
                }
            }
        }
        __syncthreads();
        if (kc + 3 < NKC) load_stage(buf, kc + 3);
        CP_COMMIT();
    }

    // epilogue: add bias, store
    #pragma unroll
    for (int mi = 0; mi < 2; mi++) {
        const int row = bm * MT + m0 + mi * 16 + (l >> 2);
        #pragma unroll
        for (int nj = 0; nj < 4; nj++) {
            const int gcol = bn * NT + n0 + nj * 8 + (l & 3) * 2;
            const float b0 = bias[gcol], b1 = bias[gcol + 1];
            float2 v0 = make_float2(acc[mi][nj][0] + b0, acc[mi][nj][1] + b1);
            float2 v1 = make_float2(acc[mi][nj][2] + b0, acc[mi][nj][3] + b1);
            *reinterpret_cast<float2*>(out + (size_t)row * H_DIM + gcol) = v0;
            *reinterpret_cast<float2*>(out + (size_t)(row + 8) * H_DIM + gcol) = v1;
        }
    }
}

// ---------------------------------------------------------------------------
extern "C" void kernel_launch(void* const* d_in, const int* in_sizes, int n_in,
                              void* d_out, int out_size) {
    const float* og   = (const float*)d_in[0];   // (B, H)
    const float* enh  = (const float*)d_in[1];   // (S, B, H)
    const float* Wm   = (const float*)d_in[2];   // (H, H)
    const float* bias = (const float*)d_in[3];   // (H,)
    float* out = (float*)d_out;                  // (B, H)

    cudaFuncSetAttribute(gemm_hmma, cudaFuncAttributeMaxDynamicSharedMemorySize,
                         SM_GEMM);

    onorm_kernel<<<B_DIM, 256>>>(og);
    convw_kernel<<<(H_DIM * H_DIM / 4) / 256, 256>>>(Wm);
    sims_kernel<<<dim3(B_DIM, S_DIM), 256>>>(og, enh);
    wr_kernel<<<(B_DIM * H_DIM / 4) / 256, 256>>>(enh);
    gemm_hmma<<<dim3(H_DIM / NT, B_DIM / MT), 256, SM_GEMM>>>(bias, out);
}

// round 4
// speedup vs baseline: 2.1761x; 1.0813x over previous
#include <cuda_runtime.h>
#include <cuda_bf16.h>
#include <math.h>
#include <stdint.h>

#define S_DIM 16
#define B_DIM 512
#define H_DIM 2048
#define EPS 1e-8f

// ---------------------------------------------------------------------------
// Device scratch
// ---------------------------------------------------------------------------
__device__ __align__(16) __nv_bfloat16 g_Ahi[B_DIM * H_DIM];
__device__ __align__(16) __nv_bfloat16 g_Alo[B_DIM * H_DIM];
__device__ __align__(16) __nv_bfloat16 g_Whi[H_DIM * H_DIM];
__device__ __align__(16) __nv_bfloat16 g_Wlo[H_DIM * H_DIM];

// ---------------------------------------------------------------------------
// PTX helpers (sm_80/90 baseline only — harness PTX target is sm_103, no 'a')
// ---------------------------------------------------------------------------
__device__ __forceinline__ uint32_t smem_u32(const void* p) {
    uint32_t r;
    asm("{ .reg .u64 t; cvta.to.shared.u64 t, %1; cvt.u32.u64 %0, t; }"
        : "=r"(r) : "l"(p));
    return r;
}
__device__ __forceinline__ void cpa16(uint32_t dst, const void* src) {
    asm volatile("cp.async.cg.shared.global [%0], [%1], 16;" :: "r"(dst), "l"(src));
}
#define CP_COMMIT() asm volatile("cp.async.commit_group;" ::: "memory")
#define CP_WAIT1()  asm volatile("cp.async.wait_group 1;" ::: "memory")

__device__ __forceinline__ void ldsm4(uint32_t* r, uint32_t addr) {
    asm volatile("ldmatrix.sync.aligned.m8n8.x4.shared.b16 {%0,%1,%2,%3}, [%4];"
                 : "=r"(r[0]), "=r"(r[1]), "=r"(r[2]), "=r"(r[3]) : "r"(addr));
}
__device__ __forceinline__ void mma16816(float* d, const uint32_t* a,
                                         uint32_t b0, uint32_t b1) {
    asm volatile(
        "mma.sync.aligned.m16n8k16.row.col.f32.bf16.bf16.f32 "
        "{%0,%1,%2,%3}, {%4,%5,%6,%7}, {%8,%9}, {%0,%1,%2,%3};"
        : "+f"(d[0]), "+f"(d[1]), "+f"(d[2]), "+f"(d[3])
        : "r"(a[0]), "r"(a[1]), "r"(a[2]), "r"(a[3]), "r"(b0), "r"(b1));
}
__device__ __forceinline__ float dot4(float4 a, float4 b) {
    return a.x * b.x + a.y * b.y + a.z * b.z + a.w * b.w;
}

// ---------------------------------------------------------------------------
// Kernel 1 (fused): norms + sims + weightedRep -> bf16 hi/lo
// One CTA per b. enhanced[.,b,.] staged in 128KB smem, read from HBM ONCE.
// ---------------------------------------------------------------------------
#define FUSED_SMEM (S_DIM * (H_DIM / 4) * 16)   // 16 * 512 float4 = 131072 B

__global__ void __launch_bounds__(256, 1)
fused_prep(const float* __restrict__ og, const float* __restrict__ enh) {
    extern __shared__ float4 se[];               // [S_DIM][H_DIM/4]
    __shared__ float red_d[S_DIM][8], red_e[S_DIM][8], red_o[8];
    __shared__ float sh_sims[S_DIM];

    const int b = blockIdx.x;
    const int tid = threadIdx.x;
    const int wid = tid >> 5, lid = tid & 31;

    // OG row in registers
    const float4* og4 = reinterpret_cast<const float4*>(og) + (size_t)b * (H_DIM / 4);
    const float4 ogv0 = og4[tid];
    const float4 ogv1 = og4[tid + 256];
    float o2 = dot4(ogv0, ogv0) + dot4(ogv1, ogv1);

    // stream enhanced rows -> smem, accumulating dot & e2 per s
    const float4* e4 = reinterpret_cast<const float4*>(enh);
    float dots[S_DIM], e2s[S_DIM];
    #pragma unroll
    for (int s = 0; s < S_DIM; s++) {
        const size_t base = ((size_t)s * B_DIM + b) * (H_DIM / 4);
        float4 v0 = e4[base + tid];
        float4 v1 = e4[base + tid + 256];
        se[s * (H_DIM / 4) + tid] = v0;
        se[s * (H_DIM / 4) + tid + 256] = v1;
        dots[s] = dot4(v0, ogv0) + dot4(v1, ogv1);
        e2s[s]  = dot4(v0, v0) + dot4(v1, v1);
    }

    // warp reductions
    #pragma unroll
    for (int o = 16; o; o >>= 1) {
        o2 += __shfl_xor_sync(0xffffffffu, o2, o);
        #pragma unroll
        for (int s = 0; s < S_DIM; s++) {
            dots[s] += __shfl_xor_sync(0xffffffffu, dots[s], o);
            e2s[s]  += __shfl_xor_sync(0xffffffffu, e2s[s], o);
        }
    }
    if (lid == 0) {
        red_o[wid] = o2;
        #pragma unroll
        for (int s = 0; s < S_DIM; s++) {
            red_d[s][wid] = dots[s];
            red_e[s][wid] = e2s[s];
        }
    }
    __syncthreads();

    if (tid < S_DIM) {
        float d = 0.f, q = 0.f, oo = 0.f;
        #pragma unroll
        for (int w = 0; w < 8; w++) {
            d += red_d[tid][w];
            q += red_e[tid][w];
            oo += red_o[w];
        }
        const float denom = fmaxf(sqrtf(q) * sqrtf(oo), EPS);
        sh_sims[tid] = (d / denom) * (1.0f / S_DIM);
    }
    __syncthreads();

    // weighted sum from smem, split to bf16 hi/lo
    float w[S_DIM];
    #pragma unroll
    for (int s = 0; s < S_DIM; s++) w[s] = sh_sims[s];

    #pragma unroll
    for (int j = 0; j < 2; j++) {
        const int slot = tid + j * 256;
        float4 acc = make_float4(0.f, 0.f, 0.f, 0.f);
        #pragma unroll
        for (int s = 0; s < S_DIM; s++) {
            float4 v = se[s * (H_DIM / 4) + slot];
            acc.x += v.x * w[s]; acc.y += v.y * w[s];
            acc.z += v.z * w[s]; acc.w += v.w * w[s];
        }
        float vv[4] = {acc.x, acc.y, acc.z, acc.w};
        __nv_bfloat16 h[4], l[4];
        #pragma unroll
        for (int q = 0; q < 4; q++) {
            h[q] = __float2bfloat16(vv[q]);
            l[q] = __float2bfloat16(vv[q] - __bfloat162float(h[q]));
        }
        const size_t o = (size_t)b * H_DIM + (size_t)slot * 4;
        __nv_bfloat162* ph = reinterpret_cast<__nv_bfloat162*>(g_Ahi + o);
        __nv_bfloat162* pl = reinterpret_cast<__nv_bfloat162*>(g_Alo + o);
        ph[0] = __halves2bfloat162(h[0], h[1]);
        ph[1] = __halves2bfloat162(h[2], h[3]);
        pl[0] = __halves2bfloat162(l[0], l[1]);
        pl[1] = __halves2bfloat162(l[2], l[3]);
    }
}

// ---------------------------------------------------------------------------
// Kernel 2: W -> bf16 hi/lo
// ---------------------------------------------------------------------------
__global__ void convw_kernel(const float* __restrict__ W) {
    const int i = blockIdx.x * 256 + threadIdx.x;
    float4 v4 = reinterpret_cast<const float4*>(W)[i];
    float vv[4] = {v4.x, v4.y, v4.z, v4.w};
    __nv_bfloat16 h[4], l[4];
    #pragma unroll
    for (int j = 0; j < 4; j++) {
        h[j] = __float2bfloat16(vv[j]);
        l[j] = __float2bfloat16(vv[j] - __bfloat162float(h[j]));
    }
    __nv_bfloat162* ph = reinterpret_cast<__nv_bfloat162*>(g_Whi + (size_t)i * 4);
    __nv_bfloat162* pl = reinterpret_cast<__nv_bfloat162*>(g_Wlo + (size_t)i * 4);
    ph[0] = __halves2bfloat162(h[0], h[1]);
    ph[1] = __halves2bfloat162(h[2], h[3]);
    pl[0] = __halves2bfloat162(l[0], l[1]);
    pl[1] = __halves2bfloat162(l[2], l[3]);
}

// ---------------------------------------------------------------------------
// Kernel 3: HMMA GEMM  out = wr @ W^T + b   (3-product bf16 split, fp32 accum)
// 128x64 CTA tile, K-chunk 64, 3 buffers / prefetch-distance-2, ONE sync/iter.
// ---------------------------------------------------------------------------
#define MT 128
#define NT 64
#define KT 64
#define NKC (H_DIM / KT)        // 32
#define LDS 144                 // bytes per smem row (72 bf16)
#define OFF_AHI 0
#define OFF_ALO (MT * LDS)
#define OFF_BHI (2 * MT * LDS)
#define OFF_BLO (2 * MT * LDS + NT * LDS)
#define STAGE   (2 * MT * LDS + 2 * NT * LDS)  // 55296
#define SM_GEMM (3 * STAGE)                    // 165888

__global__ void __launch_bounds__(256, 1)
gemm_hmma(const float* __restrict__ bias, float* __restrict__ out) {
    extern __shared__ __align__(16) char sm[];
    const uint32_t sbase = smem_u32(sm);
    const int tid = threadIdx.x;
    const int wid = tid >> 5;
    const int l   = tid & 31;
    const int bn = blockIdx.x;          // N tile (32)
    const int bm = blockIdx.y;          // M tile (4)

    const __nv_bfloat16* gAhi = g_Ahi + (size_t)bm * MT * H_DIM;
    const __nv_bfloat16* gAlo = g_Alo + (size_t)bm * MT * H_DIM;
    const __nv_bfloat16* gBhi = g_Whi + (size_t)bn * NT * H_DIM;
    const __nv_bfloat16* gBlo = g_Wlo + (size_t)bn * NT * H_DIM;

    const int lrow = tid >> 3;          // 0..31
    const int lchk = tid & 7;           // 0..7

    auto load_stage = [&](int buf, int kb) {
        const uint32_t sb = sbase + buf * STAGE;
        const int koff = kb * KT + lchk * 8;
        #pragma unroll
        for (int rr = 0; rr < 4; rr++) {
            const int row = rr * 32 + lrow;
            const uint32_t d = sb + row * LDS + lchk * 16;
            cpa16(d + OFF_AHI, gAhi + (size_t)row * H_DIM + koff);
            cpa16(d + OFF_ALO, gAlo + (size_t)row * H_DIM + koff);
        }
        #pragma unroll
        for (int rr = 0; rr < 2; rr++) {
            const int row = rr * 32 + lrow;
            const uint32_t d = sb + row * LDS + lchk * 16;
            cpa16(d + OFF_BHI, gBhi + (size_t)row * H_DIM + koff);
            cpa16(d + OFF_BLO, gBlo + (size_t)row * H_DIM + koff);
        }
    };

    // prologue: 2 stages in flight
    load_stage(0, 0); CP_COMMIT();
    load_stage(1, 1); CP_COMMIT();

    const int m0 = (wid & 3) * 32;
    const int n0 = (wid >> 2) * 32;

    const uint32_t aoff = (uint32_t)(((l & 7) + ((l >> 3) & 1) * 8) * LDS
                                     + ((l >> 4) & 1) * 16);
    const uint32_t boff = (uint32_t)(((l & 7) + ((l >> 4) & 1) * 8) * LDS
                                     + ((l >> 3) & 1) * 16);

    float acc[2][4][4];
    #pragma unroll
    for (int mi = 0; mi < 2; mi++)
        #pragma unroll
        for (int nj = 0; nj < 4; nj++)
            #pragma unroll
            for (int q = 0; q < 4; q++) acc[mi][nj][q] = 0.f;

    for (int kc = 0; kc < NKC; kc++) {
        CP_WAIT1();                       // stage kc resident
        __syncthreads();                  // also: all warps done reading (kc-1)%3
        if (kc + 2 < NKC) {               // prefetch kc+2 into buffer (kc-1)%3
            load_stage((kc + 2) % 3, kc + 2);
        }
        CP_COMMIT();

        const uint32_t sb = sbase + (kc % 3) * STAGE;
        const uint32_t aHiB = sb + OFF_AHI + m0 * LDS + aoff;
        const uint32_t aLoB = sb + OFF_ALO + m0 * LDS + aoff;
        const uint32_t bHiB = sb + OFF_BHI + n0 * LDS + boff;
        const uint32_t bLoB = sb + OFF_BLO + n0 * LDS + boff;

        #pragma unroll
        for (int ks = 0; ks < 4; ks++) {
            uint32_t ah[2][4], al[2][4], bh[2][4], bl[2][4];
            #pragma unroll
            for (int mi = 0; mi < 2; mi++) {
                ldsm4(ah[mi], aHiB + mi * 16 * LDS + ks * 32);
                ldsm4(al[mi], aLoB + mi * 16 * LDS + ks * 32);
            }
            #pragma unroll
            for (int ng = 0; ng < 2; ng++) {
                ldsm4(bh[ng], bHiB + ng * 16 * LDS + ks * 32);
                ldsm4(bl[ng], bLoB + ng * 16 * LDS + ks * 32);
            }
            #pragma unroll
            for (int mi = 0; mi < 2; mi++) {
                #pragma unroll
                for (int nj = 0; nj < 4; nj++) {
                    const int ng = nj >> 1, sp = (nj & 1) * 2;
                    mma16816(acc[mi][nj], ah[mi], bh[ng][sp], bh[ng][sp + 1]);
                    mma16816(acc[mi][nj], ah[mi], bl[ng][sp], bl[ng][sp + 1]);
                    mma16816(acc[mi][nj], al[mi], bh[ng][sp], bh[ng][sp + 1]);
                }
            }
        }
    }

    // epilogue
    #pragma unroll
    for (int mi = 0; mi < 2; mi++) {
        const int row = bm * MT + m0 + mi * 16 + (l >> 2);
        #pragma unroll
        for (int nj = 0; nj < 4; nj++) {
            const int gcol = bn * NT + n0 + nj * 8 + (l & 3) * 2;
            const float b0 = bias[gcol], b1 = bias[gcol + 1];
            float2 v0 = make_float2(acc[mi][nj][0] + b0, acc[mi][nj][1] + b1);
            float2 v1 = make_float2(acc[mi][nj][2] + b0, acc[mi][nj][3] + b1);
            *reinterpret_cast<float2*>(out + (size_t)row * H_DIM + gcol) = v0;
            *reinterpret_cast<float2*>(out + (size_t)(row + 8) * H_DIM + gcol) = v1;
        }
    }
}

// ---------------------------------------------------------------------------
extern "C" void kernel_launch(void* const* d_in, const int* in_sizes, int n_in,
                              void* d_out, int out_size) {
    const float* og   = (const float*)d_in[0];   // (B, H)
    const float* enh  = (const float*)d_in[1];   // (S, B, H)
    const float* Wm   = (const float*)d_in[2];   // (H, H)
    const float* bias = (const float*)d_in[3];   // (H,)
    float* out = (float*)d_out;                  // (B, H)

    cudaFuncSetAttribute(gemm_hmma, cudaFuncAttributeMaxDynamicSharedMemorySize,
                         SM_GEMM);
    cudaFuncSetAttribute(fused_prep, cudaFuncAttributeMaxDynamicSharedMemorySize,
                         FUSED_SMEM);

    convw_kernel<<<(H_DIM * H_DIM / 4) / 256, 256>>>(Wm);
    fused_prep<<<B_DIM, 256, FUSED_SMEM>>>(og, enh);
    gemm_hmma<<<dim3(H_DIM / NT, B_DIM / MT), 256, SM_GEMM>>>(bias, out);
}

// round 5
// speedup vs baseline: 2.4313x; 1.1173x over previous
#include <cuda_runtime.h>
#include <cuda_bf16.h>
#include <math.h>
#include <stdint.h>

#define S_DIM 16
#define B_DIM 512
#define H_DIM 2048
#define EPS 1e-8f

// ---------------------------------------------------------------------------
// Device scratch
// ---------------------------------------------------------------------------
__device__ __align__(16) __nv_bfloat16 g_Ahi[B_DIM * H_DIM];
__device__ __align__(16) __nv_bfloat16 g_Alo[B_DIM * H_DIM];

// ---------------------------------------------------------------------------
// PTX helpers (sm_80/90 baseline only — harness PTX target is sm_103, no 'a')
// ---------------------------------------------------------------------------
__device__ __forceinline__ uint32_t smem_u32(const void* p) {
    uint32_t r;
    asm("{ .reg .u64 t; cvta.to.shared.u64 t, %1; cvt.u32.u64 %0, t; }"
        : "=r"(r) : "l"(p));
    return r;
}
__device__ __forceinline__ void cpa16(uint32_t dst, const void* src) {
    asm volatile("cp.async.cg.shared.global [%0], [%1], 16;" :: "r"(dst), "l"(src));
}
#define CP_COMMIT() asm volatile("cp.async.commit_group;" ::: "memory")
#define CP_WAIT2()  asm volatile("cp.async.wait_group 2;" ::: "memory")

__device__ __forceinline__ void ldsm4(uint32_t* r, uint32_t addr) {
    asm volatile("ldmatrix.sync.aligned.m8n8.x4.shared.b16 {%0,%1,%2,%3}, [%4];"
                 : "=r"(r[0]), "=r"(r[1]), "=r"(r[2]), "=r"(r[3]) : "r"(addr));
}
__device__ __forceinline__ void mma16816(float* d, const uint32_t* a,
                                         uint32_t b0, uint32_t b1) {
    asm volatile(
        "mma.sync.aligned.m16n8k16.row.col.f32.bf16.bf16.f32 "
        "{%0,%1,%2,%3}, {%4,%5,%6,%7}, {%8,%9}, {%0,%1,%2,%3};"
        : "+f"(d[0]), "+f"(d[1]), "+f"(d[2]), "+f"(d[3])
        : "r"(a[0]), "r"(a[1]), "r"(a[2]), "r"(a[3]), "r"(b0), "r"(b1));
}
__device__ __forceinline__ float dot4(float4 a, float4 b) {
    return a.x * b.x + a.y * b.y + a.z * b.z + a.w * b.w;
}
// fp32 pair -> bf16 hi pair + bf16 lo pair (packed as u32)
__device__ __forceinline__ void split2(float x, float y, uint32_t& h, uint32_t& l) {
    __nv_bfloat162 hh = __floats2bfloat162_rn(x, y);
    float hx = __bfloat162float(__low2bfloat16(hh));
    float hy = __bfloat162float(__high2bfloat16(hh));
    __nv_bfloat162 ll = __floats2bfloat162_rn(x - hx, y - hy);
    h = *reinterpret_cast<uint32_t*>(&hh);
    l = *reinterpret_cast<uint32_t*>(&ll);
}

// ---------------------------------------------------------------------------
// Kernel 1 (fused): norms + sims + weightedRep -> bf16 hi/lo
// One CTA per b. enhanced[.,b,.] staged in 128KB smem, read from HBM ONCE.
// ---------------------------------------------------------------------------
#define FUSED_SMEM (S_DIM * (H_DIM / 4) * 16)   // 131072 B

__global__ void __launch_bounds__(256, 1)
fused_prep(const float* __restrict__ og, const float* __restrict__ enh) {
    extern __shared__ float4 se[];               // [S_DIM][H_DIM/4]
    __shared__ float red_d[S_DIM][8], red_e[S_DIM][8], red_o[8];
    __shared__ float sh_sims[S_DIM];

    const int b = blockIdx.x;
    const int tid = threadIdx.x;
    const int wid = tid >> 5, lid = tid & 31;

    const float4* og4 = reinterpret_cast<const float4*>(og) + (size_t)b * (H_DIM / 4);
    const float4 ogv0 = og4[tid];
    const float4 ogv1 = og4[tid + 256];
    float o2 = dot4(ogv0, ogv0) + dot4(ogv1, ogv1);

    const float4* e4 = reinterpret_cast<const float4*>(enh);
    float dots[S_DIM], e2s[S_DIM];
    #pragma unroll
    for (int s = 0; s < S_DIM; s++) {
        const size_t base = ((size_t)s * B_DIM + b) * (H_DIM / 4);
        float4 v0 = e4[base + tid];
        float4 v1 = e4[base + tid + 256];
        se[s * (H_DIM / 4) + tid] = v0;
        se[s * (H_DIM / 4) + tid + 256] = v1;
        dots[s] = dot4(v0, ogv0) + dot4(v1, ogv1);
        e2s[s]  = dot4(v0, v0) + dot4(v1, v1);
    }

    #pragma unroll
    for (int o = 16; o; o >>= 1) {
        o2 += __shfl_xor_sync(0xffffffffu, o2, o);
        #pragma unroll
        for (int s = 0; s < S_DIM; s++) {
            dots[s] += __shfl_xor_sync(0xffffffffu, dots[s], o);
            e2s[s]  += __shfl_xor_sync(0xffffffffu, e2s[s], o);
        }
    }
    if (lid == 0) {
        red_o[wid] = o2;
        #pragma unroll
        for (int s = 0; s < S_DIM; s++) {
            red_d[s][wid] = dots[s];
            red_e[s][wid] = e2s[s];
        }
    }
    __syncthreads();

    if (tid < S_DIM) {
        float d = 0.f, q = 0.f, oo = 0.f;
        #pragma unroll
        for (int w = 0; w < 8; w++) {
            d += red_d[tid][w];
            q += red_e[tid][w];
            oo += red_o[w];
        }
        const float denom = fmaxf(sqrtf(q) * sqrtf(oo), EPS);
        sh_sims[tid] = (d / denom) * (1.0f / S_DIM);
    }
    __syncthreads();

    float w[S_DIM];
    #pragma unroll
    for (int s = 0; s < S_DIM; s++) w[s] = sh_sims[s];

    #pragma unroll
    for (int j = 0; j < 2; j++) {
        const int slot = tid + j * 256;
        float4 acc = make_float4(0.f, 0.f, 0.f, 0.f);
        #pragma unroll
        for (int s = 0; s < S_DIM; s++) {
            float4 v = se[s * (H_DIM / 4) + slot];
            acc.x += v.x * w[s]; acc.y += v.y * w[s];
            acc.z += v.z * w[s]; acc.w += v.w * w[s];
        }
        uint32_t h0, l0, h1, l1;
        split2(acc.x, acc.y, h0, l0);
        split2(acc.z, acc.w, h1, l1);
        const size_t o = (size_t)b * H_DIM + (size_t)slot * 4;
        *reinterpret_cast<uint2*>(g_Ahi + o) = make_uint2(h0, h1);
        *reinterpret_cast<uint2*>(g_Alo + o) = make_uint2(l0, l1);
    }
}

// ---------------------------------------------------------------------------
// Kernel 2: HMMA GEMM  out = wr @ W^T + b   (3-product bf16 split, fp32 accum)
// A (hi/lo bf16) via 4-stage cp.async; B = W fp32 loaded via register
// prefetch, converted to bf16 hi/lo in-kernel (double-buffered smem).
// CTA tile 128(M) x 64(N), K-chunk 64.
// ---------------------------------------------------------------------------
#define MT 128
#define NT 64
#define KT 64
#define NKC (H_DIM / KT)        // 32
#define LDS 144                 // bytes per smem row (72 bf16)
#define OFF_ALO (MT * LDS)                  // 18432
#define ASTAGE  (2 * MT * LDS)              // 36864
#define BBASE   (4 * ASTAGE)                // 147456
#define BSTAGE  (2 * NT * LDS)              // 18432 (hi + lo)
#define OFF_BLO (NT * LDS)                  // 9216
#define SM_GEMM (BBASE + 2 * BSTAGE)        // 184320

__global__ void __launch_bounds__(256, 1)
gemm_hmma(const float* __restrict__ Wm, const float* __restrict__ bias,
          float* __restrict__ out) {
    extern __shared__ __align__(16) char sm[];
    const uint32_t sbase = smem_u32(sm);
    const int tid = threadIdx.x;
    const int wid = tid >> 5;
    const int l   = tid & 31;
    const int bn = blockIdx.x;          // N tile (32)
    const int bm = blockIdx.y;          // M tile (4)

    const __nv_bfloat16* gAhi = g_Ahi + (size_t)bm * MT * H_DIM;
    const __nv_bfloat16* gAlo = g_Alo + (size_t)bm * MT * H_DIM;

    // A loader mapping
    const int lrow = tid >> 3;          // 0..31
    const int lchk = tid & 7;           // 0..7

    auto load_stageA = [&](int buf, int kb) {
        const uint32_t sb = sbase + buf * ASTAGE;
        const int koff = kb * KT + lchk * 8;
        #pragma unroll
        for (int rr = 0; rr < 4; rr++) {
            const int row = rr * 32 + lrow;
            const uint32_t d = sb + row * LDS + lchk * 16;
            cpa16(d, gAhi + (size_t)row * H_DIM + koff);
            cpa16(d + OFF_ALO, gAlo + (size_t)row * H_DIM + koff);
        }
    };

    // B loader mapping: 64 rows x 64 fp32 cols; thread -> row=tid>>2, 16-col quad
    const int brow = tid >> 2;          // 0..63
    const int bq   = (tid & 3) * 16;    // col base
    const float* wrow = Wm + (size_t)(bn * NT + brow) * H_DIM + bq;

    float4 breg[4];
    auto ldg_B = [&](int kb) {
        const float* p = wrow + kb * KT;
        #pragma unroll
        for (int f = 0; f < 4; f++)
            breg[f] = *reinterpret_cast<const float4*>(p + f * 4);
    };
    auto sts_B = [&](int buf) {
        const uint32_t bb = sbase + BBASE + buf * BSTAGE + brow * LDS + bq * 2;
        #pragma unroll
        for (int f = 0; f < 4; f++) {
            uint32_t h0, l0, h1, l1;
            split2(breg[f].x, breg[f].y, h0, l0);
            split2(breg[f].z, breg[f].w, h1, l1);
            *reinterpret_cast<uint2*>(sm + (bb + f * 8) - sbase + 0) = make_uint2(h0, h1);
            *reinterpret_cast<uint2*>(sm + (bb + f * 8) - sbase + OFF_BLO) = make_uint2(l0, l1);
        }
    };

    // prologue: A stages 0,1,2 in flight; B(0) in smem, B(1) in regs
    ldg_B(0);
    load_stageA(0, 0); CP_COMMIT();
    load_stageA(1, 1); CP_COMMIT();
    load_stageA(2, 2); CP_COMMIT();
    sts_B(0);
    ldg_B(1);

    const int m0 = (wid & 3) * 32;
    const int n0 = (wid >> 2) * 32;

    const uint32_t aoff = (uint32_t)(((l & 7) + ((l >> 3) & 1) * 8) * LDS
                                     + ((l >> 4) & 1) * 16);
    const uint32_t boff = (uint32_t)(((l & 7) + ((l >> 4) & 1) * 8) * LDS
                                     + ((l >> 3) & 1) * 16);

    float acc[2][4][4];
    #pragma unroll
    for (int mi = 0; mi < 2; mi++)
        #pragma unroll
        for (int nj = 0; nj < 4; nj++)
            #pragma unroll
            for (int q = 0; q < 4; q++) acc[mi][nj][q] = 0.f;

    for (int kc = 0; kc < NKC; kc++) {
        CP_WAIT2();                       // A stage kc resident
        __syncthreads();                  // everyone done with stage/buf kc-1
        if (kc + 1 < NKC) sts_B((kc + 1) & 1);      // publish B(kc+1)
        if (kc + 3 < NKC) load_stageA((kc + 3) & 3, kc + 3);
        CP_COMMIT();
        if (kc + 2 < NKC) ldg_B(kc + 2);  // prefetch B(kc+2) into regs

        const uint32_t sa = sbase + (kc & 3) * ASTAGE;
        const uint32_t sb = sbase + BBASE + (kc & 1) * BSTAGE;
        const uint32_t aHiB = sa + m0 * LDS + aoff;
        const uint32_t aLoB = sa + OFF_ALO + m0 * LDS + aoff;
        const uint32_t bHiB = sb + n0 * LDS + boff;
        const uint32_t bLoB = sb + OFF_BLO + n0 * LDS + boff;

        #pragma unroll
        for (int ks = 0; ks < 4; ks++) {
            uint32_t ah[2][4], al[2][4], bh[2][4], bl[2][4];
            #pragma unroll
            for (int mi = 0; mi < 2; mi++) {
                ldsm4(ah[mi], aHiB + mi * 16 * LDS + ks * 32);
                ldsm4(al[mi], aLoB + mi * 16 * LDS + ks * 32);
            }
            #pragma unroll
            for (int ng = 0; ng < 2; ng++) {
                ldsm4(bh[ng], bHiB + ng * 16 * LDS + ks * 32);
                ldsm4(bl[ng], bLoB + ng * 16 * LDS + ks * 32);
            }
            #pragma unroll
            for (int mi = 0; mi < 2; mi++) {
                #pragma unroll
                for (int nj = 0; nj < 4; nj++) {
                    const int ng = nj >> 1, sp = (nj & 1) * 2;
                    mma16816(acc[mi][nj], ah[mi], bh[ng][sp], bh[ng][sp + 1]);
                    mma16816(acc[mi][nj], ah[mi], bl[ng][sp], bl[ng][sp + 1]);
                    mma16816(acc[mi][nj], al[mi], bh[ng][sp], bh[ng][sp + 1]);
                }
            }
        }
    }

    // epilogue
    #pragma unroll
    for (int mi = 0; mi < 2; mi++) {
        const int row = bm * MT + m0 + mi * 16 + (l >> 2);
        #pragma unroll
        for (int nj = 0; nj < 4; nj++) {
            const int gcol = bn * NT + n0 + nj * 8 + (l & 3) * 2;
            const float b0 = bias[gcol], b1 = bias[gcol + 1];
            float2 v0 = make_float2(acc[mi][nj][0] + b0, acc[mi][nj][1] + b1);
            float2 v1 = make_float2(acc[mi][nj][2] + b0, acc[mi][nj][3] + b1);
            *reinterpret_cast<float2*>(out + (size_t)row * H_DIM + gcol) = v0;
            *reinterpret_cast<float2*>(out + (size_t)(row + 8) * H_DIM + gcol) = v1;
        }
    }
}

// ---------------------------------------------------------------------------
extern "C" void kernel_launch(void* const* d_in, const int* in_sizes, int n_in,
                              void* d_out, int out_size) {
    const float* og   = (const float*)d_in[0];   // (B, H)
    const float* enh  = (const float*)d_in[1];   // (S, B, H)
    const float* Wm   = (const float*)d_in[2];   // (H, H)
    const float* bias = (const float*)d_in[3];   // (H,)
    float* out = (float*)d_out;                  // (B, H)

    cudaFuncSetAttribute(gemm_hmma, cudaFuncAttributeMaxDynamicSharedMemorySize,
                         SM_GEMM);
    cudaFuncSetAttribute(fused_prep, cudaFuncAttributeMaxDynamicSharedMemorySize,
                         FUSED_SMEM);

    fused_prep<<<B_DIM, 256, FUSED_SMEM>>>(og, enh);
    gemm_hmma<<<dim3(H_DIM / NT, B_DIM / MT), 256, SM_GEMM>>>(Wm, bias, out);
}